// round 4
// baseline (speedup 1.0000x reference)
#include <cuda_runtime.h>
#include <math.h>

#define T_STEPS 12
#define NN      10000
#define NE      320000
#define IN_DIM  64
#define HID     128
#define EMB     64
#define G3      192             // 3*EMB
#define FTOT    (T_STEPS*EMB)   // 768 batched features
#define NROWS   (NN*T_STEPS)    // 120000
#define NROWSP  120064          // padded to multiple of 128

// ---------------- scratch (static device allocations only) ----------------
__device__ float d_dinv[NN];
__device__ int   d_cnt[NN];
__device__ int   d_off[NN+1];
__device__ int   d_fill[NN];
__device__ int   d_src[NE];
__device__ float d_w[NE];
__device__ float d_AX[(size_t)NROWSP*IN_DIM];  // (ÂX) batched  [row=n*12+t][64]
__device__ float d_H1[(size_t)NROWSP*HID];     // relu(AX@W1+b1)
__device__ float d_H2[(size_t)NROWSP*EMB];     // H1@W2
__device__ float d_Z [(size_t)NROWSP*EMB];     // z_seq [row=n*12+t][64]
__device__ float d_GI[(size_t)NROWSP*G3];      // Z@W_ih^T + b_ih (all steps)
__device__ float d_h [(size_t)NN*EMB];         // GRU hidden
__device__ float d_WtIH[EMB*G3];               // W_ih transposed -> [k][3H]
__device__ float d_WtHH[EMB*G3];

// ---------------- preprocessing ----------------
__global__ void k_init() {
    int i = blockIdx.x*blockDim.x + threadIdx.x;
    if (i < NN*EMB) d_h[i] = 0.f;
    if (i < NN) { d_dinv[i] = 1.0f; d_cnt[i] = 0; }   // self-loop weight pre-added
}

__global__ void k_deg_hist(const int* __restrict__ ei, const float* __restrict__ ew) {
    int e = blockIdx.x*blockDim.x + threadIdx.x;
    if (e >= NE) return;
    int c = ei[NE + e];
    atomicAdd(&d_dinv[c], ew[e]);
    atomicAdd(&d_cnt[c], 1);
}

__global__ void k_rsqrt() {
    int i = blockIdx.x*blockDim.x + threadIdx.x;
    if (i < NN) d_dinv[i] = rsqrtf(d_dinv[i]);
}

__global__ void k_scan() {
    __shared__ int sh[1024];
    __shared__ int carry;
    int tid = threadIdx.x;
    if (tid == 0) carry = 0;
    __syncthreads();
    const int nch = (NN + 1023) / 1024;
    for (int c = 0; c < nch; c++) {
        int base = carry;
        int i = c*1024 + tid;
        int v = (i < NN) ? d_cnt[i] : 0;
        sh[tid] = v;
        __syncthreads();
        for (int ofs = 1; ofs < 1024; ofs <<= 1) {
            int t = (tid >= ofs) ? sh[tid-ofs] : 0;
            __syncthreads();
            sh[tid] += t;
            __syncthreads();
        }
        int excl = sh[tid] - v + base;
        if (i < NN) { d_off[i] = excl; d_fill[i] = excl; }
        __syncthreads();
        if (tid == 0) carry = base + sh[1023];
        __syncthreads();
    }
    if (tid == 0) d_off[NN] = carry;
}

__global__ void k_scatter(const int* __restrict__ ei, const float* __restrict__ ew) {
    int e = blockIdx.x*blockDim.x + threadIdx.x;
    if (e >= NE) return;
    int r = ei[e];
    int c = ei[NE + e];
    float nm = d_dinv[r] * ew[e] * d_dinv[c];
    int pos = atomicAdd(&d_fill[c], 1);
    d_src[pos] = r;
    d_w[pos]   = nm;
}

__global__ void k_transposeW(const float* __restrict__ W_ih, const float* __restrict__ W_hh) {
    int idx = blockIdx.x*blockDim.x + threadIdx.x;   // over G3*EMB
    if (idx >= G3*EMB) return;
    int j = idx >> 6, k = idx & 63;
    d_WtIH[k*G3 + j] = W_ih[idx];
    d_WtHH[k*G3 + j] = W_hh[idx];
}

// ---------------- batched SpMM: AX = Â X  (all 12 timesteps) ----------------
__global__ void k_spmmX(const float* __restrict__ X) {   // X = x_seq [T][N][64]
    int d = blockIdx.x;
    int j = blockIdx.y*256 + threadIdx.x;   // 0..767
    int t = j >> 6, k = j & 63;
    float di = d_dinv[d];
    float acc = di*di * X[(size_t)t*NN*IN_DIM + (size_t)d*IN_DIM + k];
    int beg = d_off[d], end = d_off[d+1];
    for (int p = beg; p < end; p++) {
        int s = d_src[p]; float w = d_w[p];
        acc += w * X[(size_t)t*NN*IN_DIM + (size_t)s*IN_DIM + k];
    }
    // row = d*12 + t, col = k
    d_AX[(size_t)(d*T_STEPS + t)*IN_DIM + k] = acc;
}

// ---------------- tiled GEMM:  C[M,N] = act(A@B + bias) ----------------
// A [NROWSP,K] row-major, B [K,N] row-major. BM=128, BN=64, BK=32, 256 thr, 8x4 micro.
template<int K, int ACT>
__global__ void __launch_bounds__(256)
k_gemmT(const float* __restrict__ A, const float* __restrict__ B,
        const float* __restrict__ bias, float* __restrict__ C, int N) {
    __shared__ float As[32][132];
    __shared__ float Bs[32][64];
    int tid = threadIdx.x;
    int tr = tid >> 4, tc = tid & 15;
    int row0 = blockIdx.x * 128;
    int col0 = blockIdx.y * 64;
    float acc[8][4];
    #pragma unroll
    for (int u = 0; u < 8; u++)
        #pragma unroll
        for (int v = 0; v < 4; v++) acc[u][v] = 0.f;

    #pragma unroll
    for (int k0 = 0; k0 < K; k0 += 32) {
        // A tile 128x32 via float4 (1024 ld.128)
        #pragma unroll
        for (int p = 0; p < 4; p++) {
            int idx = p*256 + tid;             // 0..1023
            int r = idx >> 3, k4 = (idx & 7)*4;
            float4 av = *(const float4*)&A[(size_t)(row0 + r)*K + k0 + k4];
            As[k4+0][r] = av.x; As[k4+1][r] = av.y;
            As[k4+2][r] = av.z; As[k4+3][r] = av.w;
        }
        // B tile 32x64 via float4 (512 ld.128)
        #pragma unroll
        for (int p = 0; p < 2; p++) {
            int idx = p*256 + tid;             // 0..511
            int kk = idx >> 4, c4 = (idx & 15)*4;
            float4 bv = *(const float4*)&B[(size_t)(k0 + kk)*N + col0 + c4];
            *(float4*)&Bs[kk][c4] = bv;
        }
        __syncthreads();
        #pragma unroll
        for (int k = 0; k < 32; k++) {
            float4 a0 = *(const float4*)&As[k][tr*8];
            float4 a1 = *(const float4*)&As[k][tr*8 + 4];
            float4 b0 = *(const float4*)&Bs[k][tc*4];
            float a[8] = {a0.x,a0.y,a0.z,a0.w,a1.x,a1.y,a1.z,a1.w};
            float b[4] = {b0.x,b0.y,b0.z,b0.w};
            #pragma unroll
            for (int u = 0; u < 8; u++)
                #pragma unroll
                for (int v = 0; v < 4; v++) acc[u][v] += a[u]*b[v];
        }
        __syncthreads();
    }

    float bb[4] = {0.f,0.f,0.f,0.f};
    if (bias) {
        #pragma unroll
        for (int v = 0; v < 4; v++) bb[v] = bias[col0 + tc*4 + v];
    }
    #pragma unroll
    for (int u = 0; u < 8; u++) {
        int r = row0 + tr*8 + u;
        float4 o;
        float x0 = acc[u][0] + bb[0], x1 = acc[u][1] + bb[1];
        float x2 = acc[u][2] + bb[2], x3 = acc[u][3] + bb[3];
        if (ACT) { x0 = fmaxf(x0,0.f); x1 = fmaxf(x1,0.f); x2 = fmaxf(x2,0.f); x3 = fmaxf(x3,0.f); }
        o.x = x0; o.y = x1; o.z = x2; o.w = x3;
        *(float4*)&C[(size_t)r*N + col0 + tc*4] = o;
    }
}

// ---------------- batched SpMM: Z = Â H2 + b2 ----------------
__global__ void k_spmmZ(const float* __restrict__ b2) {
    int d = blockIdx.x;
    int j = blockIdx.y*256 + threadIdx.x;   // 0..767 over [t][k]
    int t = j >> 6, k = j & 63;
    float di = d_dinv[d];
    float acc = di*di * d_H2[(size_t)(d*T_STEPS + t)*EMB + k];
    int beg = d_off[d], end = d_off[d+1];
    for (int p = beg; p < end; p++) {
        int s = d_src[p]; float w = d_w[p];
        acc += w * d_H2[(size_t)(s*T_STEPS + t)*EMB + k];
    }
    d_Z[(size_t)(d*T_STEPS + t)*EMB + k] = acc + b2[k];
}

// ---------------- GRU step: only gh = h @ W_hh^T, gi precomputed ----------------
__global__ void __launch_bounds__(256)
k_gru2(int t, const float* __restrict__ b_hh) {
    __shared__ float hs[16][EMB];           // 16 nodes / block
    int j  = threadIdx.x;                   // 0..63
    int ty = threadIdx.y;                   // 0..3
    int nb = blockIdx.x * 16;
    int lid = ty*64 + j;
    #pragma unroll
    for (int p = 0; p < 4; p++) {
        int idx = p*256 + lid;              // 0..1023
        int nn = idx >> 6, k = idx & 63;
        hs[nn][k] = d_h[(size_t)(nb + nn)*EMB + k];
    }
    __syncthreads();
    float ar[4] = {0,0,0,0}, az[4] = {0,0,0,0}, an[4] = {0,0,0,0};
    int nlo = ty*4;
    #pragma unroll 8
    for (int k = 0; k < EMB; k++) {
        float wr = d_WtHH[k*G3 + j];
        float wz = d_WtHH[k*G3 + 64 + j];
        float wn = d_WtHH[k*G3 + 128 + j];
        #pragma unroll
        for (int m = 0; m < 4; m++) {
            float hv = hs[nlo + m][k];
            ar[m] += hv*wr; az[m] += hv*wz; an[m] += hv*wn;
        }
    }
    float br = b_hh[j], bz = b_hh[64 + j], bn = b_hh[128 + j];
    #pragma unroll
    for (int m = 0; m < 4; m++) {
        int node = nb + nlo + m;
        size_t grow = (size_t)(node*T_STEPS + t)*G3;
        float gr = d_GI[grow + j], gz = d_GI[grow + 64 + j], gn = d_GI[grow + 128 + j];
        float r  = 1.f/(1.f + __expf(-(gr + ar[m] + br)));
        float zg = 1.f/(1.f + __expf(-(gz + az[m] + bz)));
        float ng = tanhf(gn + an[m] + r*(an[m]*0.f + bn));   // ng = tanh(gn + r*(ah_n + b_hh_n))
        // NOTE: correct formula below (r multiplies hidden part incl. bias)
        ng = tanhf(gn + r*(an[m] + bn));
        float ho = hs[nlo + m][j];
        d_h[(size_t)node*EMB + j] = (1.f - zg)*ng + zg*ho;
    }
}

__global__ void k_copy_z(float* __restrict__ out) {
    int i = blockIdx.x*blockDim.x + threadIdx.x;
    if (i < NN*EMB) out[(size_t)NN*NN + i] = d_h[i];
}

// ---------------- decoder: out = softplus(z z^T + b), symmetric ----------------
__global__ void __launch_bounds__(256)
k_dec(float* __restrict__ out, const float* __restrict__ db) {
    int bi = blockIdx.y, bj = blockIdx.x;
    if (bi > bj) return;
    __shared__ __align__(16) float As[32][132];
    __shared__ __align__(16) float Bs[32][132];
    int tid = threadIdx.x;
    int tj = tid & 15, ti = tid >> 4;
    int i0 = bi*128, j0 = bj*128;
    float c[8][8];
    #pragma unroll
    for (int u = 0; u < 8; u++)
        #pragma unroll
        for (int v = 0; v < 8; v++) c[u][v] = 0.f;

    for (int kc = 0; kc < 2; kc++) {
        __syncthreads();
        for (int idx = tid; idx < 128*32; idx += 256) {
            int k = idx & 31, i = idx >> 5;
            int gi = i0 + i;
            As[k][i] = (gi < NN) ? d_h[(size_t)gi*EMB + kc*32 + k] : 0.f;
            int gj = j0 + i;
            Bs[k][i] = (gj < NN) ? d_h[(size_t)gj*EMB + kc*32 + k] : 0.f;
        }
        __syncthreads();
        #pragma unroll
        for (int k = 0; k < 32; k++) {
            float4 a0 = *(const float4*)&As[k][ti*8];
            float4 a1 = *(const float4*)&As[k][ti*8+4];
            float4 b0 = *(const float4*)&Bs[k][tj*8];
            float4 b1 = *(const float4*)&Bs[k][tj*8+4];
            float av[8] = {a0.x,a0.y,a0.z,a0.w,a1.x,a1.y,a1.z,a1.w};
            float bv[8] = {b0.x,b0.y,b0.z,b0.w,b1.x,b1.y,b1.z,b1.w};
            #pragma unroll
            for (int u = 0; u < 8; u++)
                #pragma unroll
                for (int v = 0; v < 8; v++) c[u][v] += av[u]*bv[v];
        }
    }

    float bias = db[0];
    #pragma unroll
    for (int u = 0; u < 8; u++)
        #pragma unroll
        for (int v = 0; v < 8; v++) {
            float x = c[u][v] + bias;
            c[u][v] = fmaxf(x, 0.f) + __logf(1.f + __expf(-fabsf(x)));   // softplus
        }

    bool edge = (i0 + 128 > NN) || (j0 + 128 > NN);
    #pragma unroll
    for (int u = 0; u < 8; u++) {
        int gi = i0 + ti*8 + u;
        if (gi >= NN) continue;
        if (!edge) {
            float4 s0 = make_float4(c[u][0], c[u][1], c[u][2], c[u][3]);
            float4 s1 = make_float4(c[u][4], c[u][5], c[u][6], c[u][7]);
            *(float4*)&out[(size_t)gi*NN + j0 + tj*8]     = s0;
            *(float4*)&out[(size_t)gi*NN + j0 + tj*8 + 4] = s1;
        } else {
            for (int v = 0; v < 8; v++) {
                int gj = j0 + tj*8 + v;
                if (gj < NN) out[(size_t)gi*NN + gj] = c[u][v];
            }
        }
    }
    if (bi != bj) {
        #pragma unroll
        for (int v = 0; v < 8; v++) {
            int gj = j0 + tj*8 + v;
            if (gj >= NN) continue;
            if (!edge) {
                float4 s0 = make_float4(c[0][v], c[1][v], c[2][v], c[3][v]);
                float4 s1 = make_float4(c[4][v], c[5][v], c[6][v], c[7][v]);
                *(float4*)&out[(size_t)gj*NN + i0 + ti*8]     = s0;
                *(float4*)&out[(size_t)gj*NN + i0 + ti*8 + 4] = s1;
            } else {
                for (int u = 0; u < 8; u++) {
                    int gi = i0 + ti*8 + u;
                    if (gi < NN) out[(size_t)gj*NN + gi] = c[u][v];
                }
            }
        }
    }
}

// ---------------- launch ----------------
extern "C" void kernel_launch(void* const* d_in, const int* in_sizes, int n_in,
                              void* d_out, int out_size) {
    const float* x_seq = (const float*)d_in[0];
    const int*   ei    = (const int*)d_in[1];     // int32 (jax default x64 disabled)
    const float* ew    = (const float*)d_in[2];
    const float* W1    = (const float*)d_in[3];
    const float* b1    = (const float*)d_in[4];
    const float* W2    = (const float*)d_in[5];
    const float* b2    = (const float*)d_in[6];
    const float* W_ih  = (const float*)d_in[7];
    const float* W_hh  = (const float*)d_in[8];
    const float* b_ih  = (const float*)d_in[9];
    const float* b_hh  = (const float*)d_in[10];
    const float* dbias = (const float*)d_in[11];
    float* out = (float*)d_out;

    float *pAX, *pH1, *pH2, *pZ, *pGI, *pWtIH;
    cudaGetSymbolAddress((void**)&pAX,  d_AX);
    cudaGetSymbolAddress((void**)&pH1,  d_H1);
    cudaGetSymbolAddress((void**)&pH2,  d_H2);
    cudaGetSymbolAddress((void**)&pZ,   d_Z);
    cudaGetSymbolAddress((void**)&pGI,  d_GI);
    cudaGetSymbolAddress((void**)&pWtIH, d_WtIH);

    // preprocessing
    k_init<<<(NN*EMB + 255)/256, 256>>>();
    k_deg_hist<<<(NE + 255)/256, 256>>>(ei, ew);
    k_rsqrt<<<(NN + 255)/256, 256>>>();
    k_scan<<<1, 1024>>>();
    k_scatter<<<(NE + 255)/256, 256>>>(ei, ew);
    k_transposeW<<<(G3*EMB + 255)/256, 256>>>(W_ih, W_hh);

    // encoder
    k_spmmX<<<dim3(NN, FTOT/256), 256>>>(x_seq);
    k_gemmT<IN_DIM, 1><<<dim3(NROWSP/128, 2), 256>>>(pAX, W1, b1, pH1, HID);
    k_gemmT<HID,    0><<<dim3(NROWSP/128, 1), 256>>>(pH1, W2, nullptr, pH2, EMB);
    k_spmmZ<<<dim3(NN, FTOT/256), 256>>>(b2);

    // GRU: precompute GI for all timesteps, then 12 slim steps
    k_gemmT<EMB, 0><<<dim3(NROWSP/128, 3), 256>>>(pZ, pWtIH, b_ih, pGI, G3);
    for (int t = 0; t < T_STEPS; t++)
        k_gru2<<<NN/16, dim3(64, 4)>>>(t, b_hh);

    k_copy_z<<<(NN*EMB + 255)/256, 256>>>(out);

    // decoder (symmetric)
    const int NT = (NN + 127)/128;   // 79
    k_dec<<<dim3(NT, NT), 256>>>(out, dbias);
}

// round 6
// speedup vs baseline: 1.5133x; 1.5133x over previous
#include <cuda_runtime.h>
#include <math.h>

#define T_STEPS 12
#define NN      10000
#define NE      320000
#define IN_DIM  64
#define HID     128
#define EMB     64
#define G3      192             // 3*EMB
#define FTOT    (T_STEPS*EMB)   // 768 batched features
#define NROWS   (NN*T_STEPS)    // 120000
#define NROWSP  120064          // padded to multiple of 128
#define GNODES  32              // nodes per GRU block

// ---------------- scratch (static device allocations only) ----------------
__device__ float d_dinv[NN];
__device__ int   d_cnt[NN];
__device__ int   d_off[NN+1];
__device__ int   d_fill[NN];
__device__ int   d_src[NE];
__device__ float d_w[NE];
__device__ float d_AX[(size_t)NROWSP*IN_DIM];  // (ÂX) batched  [row=n*12+t][64]
__device__ float d_H1[(size_t)NROWSP*HID];     // relu(AX@W1+b1)
__device__ float d_H2[(size_t)NROWSP*EMB];     // H1@W2
__device__ float d_Z [(size_t)NROWSP*EMB];     // z_seq [row=n*12+t][64] == [n][t*64+k]
__device__ float d_h [(size_t)NN*EMB];         // final GRU hidden
__device__ float d_WtIH[EMB*G3];               // W_ih^T -> [k][3H]
__device__ float d_WtHH[EMB*G3];

// ---------------- preprocessing ----------------
__global__ void k_init() {
    int i = blockIdx.x*blockDim.x + threadIdx.x;
    if (i < NN) { d_dinv[i] = 1.0f; d_cnt[i] = 0; }   // self-loop weight pre-added
}

__global__ void k_deg_hist(const int* __restrict__ ei, const float* __restrict__ ew) {
    int e = blockIdx.x*blockDim.x + threadIdx.x;
    if (e >= NE) return;
    int c = ei[NE + e];
    atomicAdd(&d_dinv[c], ew[e]);
    atomicAdd(&d_cnt[c], 1);
}

__global__ void k_rsqrt() {
    int i = blockIdx.x*blockDim.x + threadIdx.x;
    if (i < NN) d_dinv[i] = rsqrtf(d_dinv[i]);
}

// fast scan: 1024 threads, 10 elems/thread, warp shuffles
__global__ void k_scan() {
    __shared__ int warpsum[32];
    int tid = threadIdx.x;
    int vals[10];
    int s = 0;
    #pragma unroll
    for (int i = 0; i < 10; i++) {
        int idx = tid*10 + i;
        int v = (idx < NN) ? d_cnt[idx] : 0;
        vals[i] = s;                // exclusive prefix within thread
        s += v;
    }
    int lane = tid & 31, wid = tid >> 5;
    int tot = s;
    #pragma unroll
    for (int o = 1; o < 32; o <<= 1) {
        int n = __shfl_up_sync(0xffffffffu, tot, o);
        if (lane >= o) tot += n;
    }
    if (lane == 31) warpsum[wid] = tot;
    __syncthreads();
    if (wid == 0) {
        int w = warpsum[lane];
        #pragma unroll
        for (int o = 1; o < 32; o <<= 1) {
            int n = __shfl_up_sync(0xffffffffu, w, o);
            if (lane >= o) w += n;
        }
        warpsum[lane] = w;
    }
    __syncthreads();
    int base = tot - s + (wid ? warpsum[wid-1] : 0);   // exclusive prefix of thread
    #pragma unroll
    for (int i = 0; i < 10; i++) {
        int idx = tid*10 + i;
        if (idx < NN) { int o = base + vals[i]; d_off[idx] = o; d_fill[idx] = o; }
    }
    if (tid == 1023) d_off[NN] = base + s;
}

__global__ void k_scatter(const int* __restrict__ ei, const float* __restrict__ ew) {
    int e = blockIdx.x*blockDim.x + threadIdx.x;
    if (e >= NE) return;
    int r = ei[e];
    int c = ei[NE + e];
    float nm = d_dinv[r] * ew[e] * d_dinv[c];
    int pos = atomicAdd(&d_fill[c], 1);
    d_src[pos] = r;
    d_w[pos]   = nm;
}

__global__ void k_transposeW(const float* __restrict__ W_ih, const float* __restrict__ W_hh) {
    int idx = blockIdx.x*blockDim.x + threadIdx.x;   // over G3*EMB
    if (idx >= G3*EMB) return;
    int j = idx >> 6, k = idx & 63;
    d_WtIH[k*G3 + j] = W_ih[idx];
    d_WtHH[k*G3 + j] = W_hh[idx];
}

// ---------------- batched SpMM: AX = Â X  (unroll-4 prefetch) ----------------
__global__ void k_spmmX(const float* __restrict__ X) {   // X = x_seq [T][N][64]
    int d = blockIdx.x;
    int j = blockIdx.y*256 + threadIdx.x;   // 0..767
    int t = j >> 6, k = j & 63;
    const float* Xt = X + (size_t)t*NN*IN_DIM + k;
    float di = d_dinv[d];
    float acc = di*di * Xt[(size_t)d*IN_DIM];
    int beg = d_off[d], end = d_off[d+1];
    int p = beg;
    for (; p + 4 <= end; p += 4) {
        int   s0 = d_src[p],   s1 = d_src[p+1], s2 = d_src[p+2], s3 = d_src[p+3];
        float w0 = d_w[p],     w1 = d_w[p+1],   w2 = d_w[p+2],   w3 = d_w[p+3];
        float x0 = Xt[(size_t)s0*IN_DIM];
        float x1 = Xt[(size_t)s1*IN_DIM];
        float x2 = Xt[(size_t)s2*IN_DIM];
        float x3 = Xt[(size_t)s3*IN_DIM];
        acc += w0*x0; acc += w1*x1; acc += w2*x2; acc += w3*x3;
    }
    for (; p < end; p++) acc += d_w[p] * Xt[(size_t)d_src[p]*IN_DIM];
    d_AX[(size_t)(d*T_STEPS + t)*IN_DIM + k] = acc;
}

// ---------------- tiled GEMM: C = act(A@B + bias), BM=128 BN=64 BK=32 ----------------
template<int K, int ACT>
__global__ void __launch_bounds__(256)
k_gemmT(const float* __restrict__ A, const float* __restrict__ B,
        const float* __restrict__ bias, float* __restrict__ C, int N) {
    __shared__ float As[32][132];
    __shared__ float Bs[32][64];
    int tid = threadIdx.x;
    int tr = tid >> 4, tc = tid & 15;
    int row0 = blockIdx.x * 128;
    int col0 = blockIdx.y * 64;
    float acc[8][4];
    #pragma unroll
    for (int u = 0; u < 8; u++)
        #pragma unroll
        for (int v = 0; v < 4; v++) acc[u][v] = 0.f;

    #pragma unroll
    for (int k0 = 0; k0 < K; k0 += 32) {
        #pragma unroll
        for (int p = 0; p < 4; p++) {
            int idx = p*256 + tid;
            int r = idx >> 3, k4 = (idx & 7)*4;
            float4 av = *(const float4*)&A[(size_t)(row0 + r)*K + k0 + k4];
            As[k4+0][r] = av.x; As[k4+1][r] = av.y;
            As[k4+2][r] = av.z; As[k4+3][r] = av.w;
        }
        #pragma unroll
        for (int p = 0; p < 2; p++) {
            int idx = p*256 + tid;
            int kk = idx >> 4, c4 = (idx & 15)*4;
            float4 bv = *(const float4*)&B[(size_t)(k0 + kk)*N + col0 + c4];
            *(float4*)&Bs[kk][c4] = bv;
        }
        __syncthreads();
        #pragma unroll
        for (int k = 0; k < 32; k++) {
            float4 a0 = *(const float4*)&As[k][tr*8];
            float4 a1 = *(const float4*)&As[k][tr*8 + 4];
            float4 b0 = *(const float4*)&Bs[k][tc*4];
            float a[8] = {a0.x,a0.y,a0.z,a0.w,a1.x,a1.y,a1.z,a1.w};
            float b[4] = {b0.x,b0.y,b0.z,b0.w};
            #pragma unroll
            for (int u = 0; u < 8; u++)
                #pragma unroll
                for (int v = 0; v < 4; v++) acc[u][v] += a[u]*b[v];
        }
        __syncthreads();
    }

    float bb[4] = {0.f,0.f,0.f,0.f};
    if (bias) {
        #pragma unroll
        for (int v = 0; v < 4; v++) bb[v] = bias[col0 + tc*4 + v];
    }
    #pragma unroll
    for (int u = 0; u < 8; u++) {
        int r = row0 + tr*8 + u;
        float x0 = acc[u][0] + bb[0], x1 = acc[u][1] + bb[1];
        float x2 = acc[u][2] + bb[2], x3 = acc[u][3] + bb[3];
        if (ACT) { x0 = fmaxf(x0,0.f); x1 = fmaxf(x1,0.f); x2 = fmaxf(x2,0.f); x3 = fmaxf(x3,0.f); }
        float4 o = make_float4(x0, x1, x2, x3);
        *(float4*)&C[(size_t)r*N + col0 + tc*4] = o;
    }
}

// ---------------- batched SpMM: Z = Â H2 + b2  (unroll-4 prefetch) ----------------
__global__ void k_spmmZ(const float* __restrict__ b2) {
    int d = blockIdx.x;
    int j = blockIdx.y*256 + threadIdx.x;   // 0..767 over [t][k]
    int t = j >> 6, k = j & 63;
    const float* H = d_H2 + (size_t)t*EMB + k;   // row n -> offset n*FTOT
    float di = d_dinv[d];
    float acc = di*di * H[(size_t)d*FTOT];
    int beg = d_off[d], end = d_off[d+1];
    int p = beg;
    for (; p + 4 <= end; p += 4) {
        int   s0 = d_src[p],   s1 = d_src[p+1], s2 = d_src[p+2], s3 = d_src[p+3];
        float w0 = d_w[p],     w1 = d_w[p+1],   w2 = d_w[p+2],   w3 = d_w[p+3];
        float x0 = H[(size_t)s0*FTOT];
        float x1 = H[(size_t)s1*FTOT];
        float x2 = H[(size_t)s2*FTOT];
        float x3 = H[(size_t)s3*FTOT];
        acc += w0*x0; acc += w1*x1; acc += w2*x2; acc += w3*x3;
    }
    for (; p < end; p++) acc += d_w[p] * H[(size_t)d_src[p]*FTOT];
    d_Z[(size_t)d*FTOT + t*EMB + k] = acc + b2[k];
}

// ---------------- fused GRU: all 12 steps, h resident in shared ----------------
// 256 threads: j = tid&63 (feature), g = tid>>6; each thread owns 8 nodes (nlo=g*8).
// Layout hs/zs[k][m] (k-major, pad 36 so float4 rows stay 16B-aligned).
__global__ void __launch_bounds__(256)
k_gruF(const float* __restrict__ b_ih, const float* __restrict__ b_hh,
       float* __restrict__ out) {
    __shared__ float hs[64][GNODES+4];
    __shared__ float zs[64][GNODES+4];
    int tid = threadIdx.x;
    int j = tid & 63;
    int g = tid >> 6;
    int nlo = g * 8;
    int nb = blockIdx.x * GNODES;

    for (int idx = tid; idx < 64*GNODES; idx += 256) {
        int m = idx >> 6, k = idx & 63;
        hs[k][m] = 0.f;
    }

    float br = b_hh[j],     bz = b_hh[64+j],  bn = b_hh[128+j];
    float cr = b_ih[j],     cz = b_ih[64+j],  cn = b_ih[128+j];

    for (int t = 0; t < T_STEPS; t++) {
        __syncthreads();
        // stage z_t for the block's 32 nodes (transposed)
        for (int idx = tid; idx < 64*GNODES; idx += 256) {
            int m = idx >> 6, k = idx & 63;
            int node = nb + m;
            zs[k][m] = (node < NN) ? d_Z[(size_t)node*FTOT + t*EMB + k] : 0.f;
        }
        __syncthreads();

        float ir[8], iz[8], inx[8], hr[8], hz[8], hn[8];
        #pragma unroll
        for (int m = 0; m < 8; m++) { ir[m]=iz[m]=inx[m]=hr[m]=hz[m]=hn[m]=0.f; }

        #pragma unroll 4
        for (int k = 0; k < EMB; k++) {
            const float* wi = &d_WtIH[k*G3];
            const float* wh = &d_WtHH[k*G3];
            float wir = wi[j], wiz = wi[64+j], win = wi[128+j];
            float whr = wh[j], whz = wh[64+j], whn = wh[128+j];
            float4 za = *(const float4*)&zs[k][nlo];
            float4 zb = *(const float4*)&zs[k][nlo+4];
            float4 ha = *(const float4*)&hs[k][nlo];
            float4 hb = *(const float4*)&hs[k][nlo+4];
            float zv[8] = {za.x,za.y,za.z,za.w,zb.x,zb.y,zb.z,zb.w};
            float hv[8] = {ha.x,ha.y,ha.z,ha.w,hb.x,hb.y,hb.z,hb.w};
            #pragma unroll
            for (int m = 0; m < 8; m++) {
                ir[m]  += zv[m]*wir;  iz[m] += zv[m]*wiz;  inx[m] += zv[m]*win;
                hr[m]  += hv[m]*whr;  hz[m] += hv[m]*whz;  hn[m]  += hv[m]*whn;
            }
        }
        __syncthreads();   // all hs reads done before updates
        #pragma unroll
        for (int m = 0; m < 8; m++) {
            float r  = 1.f/(1.f + __expf(-(ir[m] + cr + hr[m] + br)));
            float zg = 1.f/(1.f + __expf(-(iz[m] + cz + hz[m] + bz)));
            float ng = tanhf(inx[m] + cn + r*(hn[m] + bn));
            float ho = hs[j][nlo + m];
            hs[j][nlo + m] = (1.f - zg)*ng + zg*ho;
        }
    }
    __syncthreads();
    // write final hidden state to d_h and to output tail
    for (int idx = tid; idx < 64*GNODES; idx += 256) {
        int m = idx >> 6, k = idx & 63;
        int node = nb + m;
        if (node < NN) {
            float v = hs[k][m];
            d_h[(size_t)node*EMB + k] = v;
            out[(size_t)NN*NN + (size_t)node*EMB + k] = v;
        }
    }
}

// ---------------- decoder: out = softplus(z z^T + b), symmetric ----------------
__global__ void __launch_bounds__(256)
k_dec(float* __restrict__ out, const float* __restrict__ db) {
    int bi = blockIdx.y, bj = blockIdx.x;
    if (bi > bj) return;
    __shared__ __align__(16) float As[32][132];
    __shared__ __align__(16) float Bs[32][132];
    int tid = threadIdx.x;
    int tj = tid & 15, ti = tid >> 4;
    int i0 = bi*128, j0 = bj*128;
    float c[8][8];
    #pragma unroll
    for (int u = 0; u < 8; u++)
        #pragma unroll
        for (int v = 0; v < 8; v++) c[u][v] = 0.f;

    for (int kc = 0; kc < 2; kc++) {
        __syncthreads();
        for (int idx = tid; idx < 128*32; idx += 256) {
            int k = idx & 31, i = idx >> 5;
            int gi = i0 + i;
            As[k][i] = (gi < NN) ? d_h[(size_t)gi*EMB + kc*32 + k] : 0.f;
            int gj = j0 + i;
            Bs[k][i] = (gj < NN) ? d_h[(size_t)gj*EMB + kc*32 + k] : 0.f;
        }
        __syncthreads();
        #pragma unroll
        for (int k = 0; k < 32; k++) {
            float4 a0 = *(const float4*)&As[k][ti*8];
            float4 a1 = *(const float4*)&As[k][ti*8+4];
            float4 b0 = *(const float4*)&Bs[k][tj*8];
            float4 b1 = *(const float4*)&Bs[k][tj*8+4];
            float av[8] = {a0.x,a0.y,a0.z,a0.w,a1.x,a1.y,a1.z,a1.w};
            float bv[8] = {b0.x,b0.y,b0.z,b0.w,b1.x,b1.y,b1.z,b1.w};
            #pragma unroll
            for (int u = 0; u < 8; u++)
                #pragma unroll
                for (int v = 0; v < 8; v++) c[u][v] += av[u]*bv[v];
        }
    }

    float bias = db[0];
    #pragma unroll
    for (int u = 0; u < 8; u++)
        #pragma unroll
        for (int v = 0; v < 8; v++) {
            float x = c[u][v] + bias;
            c[u][v] = fmaxf(x, 0.f) + __logf(1.f + __expf(-fabsf(x)));
        }

    bool edge = (i0 + 128 > NN) || (j0 + 128 > NN);
    #pragma unroll
    for (int u = 0; u < 8; u++) {
        int gi = i0 + ti*8 + u;
        if (gi >= NN) continue;
        if (!edge) {
            float4 s0 = make_float4(c[u][0], c[u][1], c[u][2], c[u][3]);
            float4 s1 = make_float4(c[u][4], c[u][5], c[u][6], c[u][7]);
            *(float4*)&out[(size_t)gi*NN + j0 + tj*8]     = s0;
            *(float4*)&out[(size_t)gi*NN + j0 + tj*8 + 4] = s1;
        } else {
            for (int v = 0; v < 8; v++) {
                int gj = j0 + tj*8 + v;
                if (gj < NN) out[(size_t)gi*NN + gj] = c[u][v];
            }
        }
    }
    if (bi != bj) {
        #pragma unroll
        for (int v = 0; v < 8; v++) {
            int gj = j0 + tj*8 + v;
            if (gj >= NN) continue;
            if (!edge) {
                float4 s0 = make_float4(c[0][v], c[1][v], c[2][v], c[3][v]);
                float4 s1 = make_float4(c[4][v], c[5][v], c[6][v], c[7][v]);
                *(float4*)&out[(size_t)gj*NN + i0 + ti*8]     = s0;
                *(float4*)&out[(size_t)gj*NN + i0 + ti*8 + 4] = s1;
            } else {
                for (int u = 0; u < 8; u++) {
                    int gi = i0 + ti*8 + u;
                    if (gi < NN) out[(size_t)gj*NN + gi] = c[u][v];
                }
            }
        }
    }
}

// ---------------- launch ----------------
extern "C" void kernel_launch(void* const* d_in, const int* in_sizes, int n_in,
                              void* d_out, int out_size) {
    const float* x_seq = (const float*)d_in[0];
    const int*   ei    = (const int*)d_in[1];     // int32 (jax x64 disabled)
    const float* ew    = (const float*)d_in[2];
    const float* W1    = (const float*)d_in[3];
    const float* b1    = (const float*)d_in[4];
    const float* W2    = (const float*)d_in[5];
    const float* b2    = (const float*)d_in[6];
    const float* W_ih  = (const float*)d_in[7];
    const float* W_hh  = (const float*)d_in[8];
    const float* b_ih  = (const float*)d_in[9];
    const float* b_hh  = (const float*)d_in[10];
    const float* dbias = (const float*)d_in[11];
    float* out = (float*)d_out;

    float *pAX, *pH1, *pH2;
    cudaGetSymbolAddress((void**)&pAX, d_AX);
    cudaGetSymbolAddress((void**)&pH1, d_H1);
    cudaGetSymbolAddress((void**)&pH2, d_H2);

    // preprocessing
    k_init<<<(NN + 255)/256, 256>>>();
    k_deg_hist<<<(NE + 255)/256, 256>>>(ei, ew);
    k_rsqrt<<<(NN + 255)/256, 256>>>();
    k_scan<<<1, 1024>>>();
    k_scatter<<<(NE + 255)/256, 256>>>(ei, ew);
    k_transposeW<<<(G3*EMB + 255)/256, 256>>>(W_ih, W_hh);

    // encoder
    k_spmmX<<<dim3(NN, FTOT/256), 256>>>(x_seq);
    k_gemmT<IN_DIM, 1><<<dim3(NROWSP/128, 2), 256>>>(pAX, W1, b1, pH1, HID);
    k_gemmT<HID,    0><<<dim3(NROWSP/128, 1), 256>>>(pH1, W2, nullptr, pH2, EMB);
    k_spmmZ<<<dim3(NN, FTOT/256), 256>>>(b2);

    // fused GRU (all 12 steps, one launch; also writes z to output tail)
    k_gruF<<<(NN + GNODES - 1)/GNODES, 256>>>(b_ih, b_hh, out);

    // decoder (symmetric)
    const int NT = (NN + 127)/128;   // 79
    k_dec<<<dim3(NT, NT), 256>>>(out, dbias);
}

// round 8
// speedup vs baseline: 1.6792x; 1.1096x over previous
#include <cuda_runtime.h>
#include <cuda_bf16.h>
#include <math.h>
#include <stdint.h>

#define T_STEPS 12
#define NN      10000
#define NE      320000
#define IN_DIM  64
#define HID     128
#define EMB     64
#define G3      192             // 3*EMB
#define FTOT    (T_STEPS*EMB)   // 768
#define NROWS   (NN*T_STEPS)    // 120000
#define NROWSP  120064
#define GNODES  32
#define NNP     10112           // 79*128

// ---------------- scratch ----------------
__device__ float d_dinv[NN];
__device__ int   d_cnt[NN];
__device__ int   d_off[NN+1];
__device__ int   d_fill[NN];
__device__ int   d_src[NE];
__device__ float d_w[NE];
__device__ float d_AX[(size_t)NROWSP*IN_DIM];
__device__ float d_H1[(size_t)NROWSP*HID];
__device__ float d_H2[(size_t)NROWSP*EMB];
__device__ float d_Z [(size_t)NROWSP*EMB];
__device__ float d_h [(size_t)NN*EMB];
__device__ float d_WtIH[EMB*G3];
__device__ float d_WtHH[EMB*G3];
__device__ __nv_bfloat16 d_Za[(size_t)NNP*EMB];   // hi part of z
__device__ __nv_bfloat16 d_Zb[(size_t)NNP*EMB];   // lo part of z

static __device__ __forceinline__ uint32_t s2u(const void* p) {
    uint32_t a;
    asm("{ .reg .u64 t; cvta.to.shared.u64 t, %1; cvt.u32.u64 %0, t; }" : "=r"(a) : "l"(p));
    return a;
}
#define LDM4(r0,r1,r2,r3,addr) \
    asm volatile("ldmatrix.sync.aligned.m8n8.x4.shared.b16 {%0,%1,%2,%3}, [%4];" \
        : "=r"(r0), "=r"(r1), "=r"(r2), "=r"(r3) : "r"(addr))
#define MMA16816(c, a, b) \
    asm volatile("mma.sync.aligned.m16n8k16.row.col.f32.bf16.bf16.f32 " \
        "{%0,%1,%2,%3}, {%4,%5,%6,%7}, {%8,%9}, {%0,%1,%2,%3};" \
        : "+f"((c)[0]), "+f"((c)[1]), "+f"((c)[2]), "+f"((c)[3]) \
        : "r"((a)[0]), "r"((a)[1]), "r"((a)[2]), "r"((a)[3]), "r"((b)[0]), "r"((b)[1]))

// ---------------- preprocessing ----------------
__global__ void k_init() {
    int i = blockIdx.x*blockDim.x + threadIdx.x;
    if (i < NN) { d_dinv[i] = 1.0f; d_cnt[i] = 0; }
}

__global__ void k_deg_hist(const int* __restrict__ ei, const float* __restrict__ ew) {
    int e = blockIdx.x*blockDim.x + threadIdx.x;
    if (e >= NE) return;
    int c = ei[NE + e];
    atomicAdd(&d_dinv[c], ew[e]);
    atomicAdd(&d_cnt[c], 1);
}

__global__ void k_rsqrt() {
    int i = blockIdx.x*blockDim.x + threadIdx.x;
    if (i < NN) d_dinv[i] = rsqrtf(d_dinv[i]);
}

__global__ void k_scan() {
    __shared__ int warpsum[32];
    int tid = threadIdx.x;
    int vals[10];
    int s = 0;
    #pragma unroll
    for (int i = 0; i < 10; i++) {
        int idx = tid*10 + i;
        int v = (idx < NN) ? d_cnt[idx] : 0;
        vals[i] = s;
        s += v;
    }
    int lane = tid & 31, wid = tid >> 5;
    int tot = s;
    #pragma unroll
    for (int o = 1; o < 32; o <<= 1) {
        int n = __shfl_up_sync(0xffffffffu, tot, o);
        if (lane >= o) tot += n;
    }
    if (lane == 31) warpsum[wid] = tot;
    __syncthreads();
    if (wid == 0) {
        int w = warpsum[lane];
        #pragma unroll
        for (int o = 1; o < 32; o <<= 1) {
            int n = __shfl_up_sync(0xffffffffu, w, o);
            if (lane >= o) w += n;
        }
        warpsum[lane] = w;
    }
    __syncthreads();
    int base = tot - s + (wid ? warpsum[wid-1] : 0);
    #pragma unroll
    for (int i = 0; i < 10; i++) {
        int idx = tid*10 + i;
        if (idx < NN) { int o = base + vals[i]; d_off[idx] = o; d_fill[idx] = o; }
    }
    if (tid == 1023) d_off[NN] = base + s;
}

__global__ void k_scatter(const int* __restrict__ ei, const float* __restrict__ ew) {
    int e = blockIdx.x*blockDim.x + threadIdx.x;
    if (e >= NE) return;
    int r = ei[e];
    int c = ei[NE + e];
    float nm = d_dinv[r] * ew[e] * d_dinv[c];
    int pos = atomicAdd(&d_fill[c], 1);
    d_src[pos] = r;
    d_w[pos]   = nm;
}

__global__ void k_transposeW(const float* __restrict__ W_ih, const float* __restrict__ W_hh) {
    int idx = blockIdx.x*blockDim.x + threadIdx.x;
    if (idx >= G3*EMB) return;
    int j = idx >> 6, k = idx & 63;
    d_WtIH[k*G3 + j] = W_ih[idx];
    d_WtHH[k*G3 + j] = W_hh[idx];
}

// ---------------- batched SpMM: AX = Â X ----------------
__global__ void k_spmmX(const float* __restrict__ X) {
    int d = blockIdx.x;
    int j = blockIdx.y*256 + threadIdx.x;
    int t = j >> 6, k = j & 63;
    const float* Xt = X + (size_t)t*NN*IN_DIM + k;
    float di = d_dinv[d];
    float acc = di*di * Xt[(size_t)d*IN_DIM];
    int beg = d_off[d], end = d_off[d+1];
    int p = beg;
    for (; p + 4 <= end; p += 4) {
        int   s0 = d_src[p],   s1 = d_src[p+1], s2 = d_src[p+2], s3 = d_src[p+3];
        float w0 = d_w[p],     w1 = d_w[p+1],   w2 = d_w[p+2],   w3 = d_w[p+3];
        float x0 = Xt[(size_t)s0*IN_DIM];
        float x1 = Xt[(size_t)s1*IN_DIM];
        float x2 = Xt[(size_t)s2*IN_DIM];
        float x3 = Xt[(size_t)s3*IN_DIM];
        acc += w0*x0; acc += w1*x1; acc += w2*x2; acc += w3*x3;
    }
    for (; p < end; p++) acc += d_w[p] * Xt[(size_t)d_src[p]*IN_DIM];
    d_AX[(size_t)(d*T_STEPS + t)*IN_DIM + k] = acc;
}

// ---------------- tiled GEMM: C = act(A@B + bias) ----------------
template<int K, int ACT>
__global__ void __launch_bounds__(256)
k_gemmT(const float* __restrict__ A, const float* __restrict__ B,
        const float* __restrict__ bias, float* __restrict__ C, int N) {
    __shared__ float As[32][132];
    __shared__ float Bs[32][64];
    int tid = threadIdx.x;
    int tr = tid >> 4, tc = tid & 15;
    int row0 = blockIdx.x * 128;
    int col0 = blockIdx.y * 64;
    float acc[8][4];
    #pragma unroll
    for (int u = 0; u < 8; u++)
        #pragma unroll
        for (int v = 0; v < 4; v++) acc[u][v] = 0.f;

    #pragma unroll
    for (int k0 = 0; k0 < K; k0 += 32) {
        #pragma unroll
        for (int p = 0; p < 4; p++) {
            int idx = p*256 + tid;
            int r = idx >> 3, k4 = (idx & 7)*4;
            float4 av = *(const float4*)&A[(size_t)(row0 + r)*K + k0 + k4];
            As[k4+0][r] = av.x; As[k4+1][r] = av.y;
            As[k4+2][r] = av.z; As[k4+3][r] = av.w;
        }
        #pragma unroll
        for (int p = 0; p < 2; p++) {
            int idx = p*256 + tid;
            int kk = idx >> 4, c4 = (idx & 15)*4;
            float4 bv = *(const float4*)&B[(size_t)(k0 + kk)*N + col0 + c4];
            *(float4*)&Bs[kk][c4] = bv;
        }
        __syncthreads();
        #pragma unroll
        for (int k = 0; k < 32; k++) {
            float4 a0 = *(const float4*)&As[k][tr*8];
            float4 a1 = *(const float4*)&As[k][tr*8 + 4];
            float4 b0 = *(const float4*)&Bs[k][tc*4];
            float a[8] = {a0.x,a0.y,a0.z,a0.w,a1.x,a1.y,a1.z,a1.w};
            float b[4] = {b0.x,b0.y,b0.z,b0.w};
            #pragma unroll
            for (int u = 0; u < 8; u++)
                #pragma unroll
                for (int v = 0; v < 4; v++) acc[u][v] += a[u]*b[v];
        }
        __syncthreads();
    }

    float bb[4] = {0.f,0.f,0.f,0.f};
    if (bias) {
        #pragma unroll
        for (int v = 0; v < 4; v++) bb[v] = bias[col0 + tc*4 + v];
    }
    #pragma unroll
    for (int u = 0; u < 8; u++) {
        int r = row0 + tr*8 + u;
        float x0 = acc[u][0] + bb[0], x1 = acc[u][1] + bb[1];
        float x2 = acc[u][2] + bb[2], x3 = acc[u][3] + bb[3];
        if (ACT) { x0 = fmaxf(x0,0.f); x1 = fmaxf(x1,0.f); x2 = fmaxf(x2,0.f); x3 = fmaxf(x3,0.f); }
        float4 o = make_float4(x0, x1, x2, x3);
        *(float4*)&C[(size_t)r*N + col0 + tc*4] = o;
    }
}

// ---------------- batched SpMM: Z = Â H2 + b2 ----------------
__global__ void k_spmmZ(const float* __restrict__ b2) {
    int d = blockIdx.x;
    int j = blockIdx.y*256 + threadIdx.x;
    int t = j >> 6, k = j & 63;
    const float* H = d_H2 + (size_t)t*EMB + k;
    float di = d_dinv[d];
    float acc = di*di * H[(size_t)d*FTOT];
    int beg = d_off[d], end = d_off[d+1];
    int p = beg;
    for (; p + 4 <= end; p += 4) {
        int   s0 = d_src[p],   s1 = d_src[p+1], s2 = d_src[p+2], s3 = d_src[p+3];
        float w0 = d_w[p],     w1 = d_w[p+1],   w2 = d_w[p+2],   w3 = d_w[p+3];
        float x0 = H[(size_t)s0*FTOT];
        float x1 = H[(size_t)s1*FTOT];
        float x2 = H[(size_t)s2*FTOT];
        float x3 = H[(size_t)s3*FTOT];
        acc += w0*x0; acc += w1*x1; acc += w2*x2; acc += w3*x3;
    }
    for (; p < end; p++) acc += d_w[p] * H[(size_t)d_src[p]*FTOT];
    d_Z[(size_t)d*FTOT + t*EMB + k] = acc + b2[k];
}

// ---------------- fused GRU ----------------
__global__ void __launch_bounds__(256)
k_gruF(const float* __restrict__ b_ih, const float* __restrict__ b_hh,
       float* __restrict__ out) {
    __shared__ float hs[64][GNODES+4];
    __shared__ float zs[64][GNODES+4];
    int tid = threadIdx.x;
    int j = tid & 63;
    int g = tid >> 6;
    int nlo = g * 8;
    int nb = blockIdx.x * GNODES;

    for (int idx = tid; idx < 64*GNODES; idx += 256) {
        int m = idx >> 6, k = idx & 63;
        hs[k][m] = 0.f;
    }

    float br = b_hh[j],     bz = b_hh[64+j],  bn = b_hh[128+j];
    float cr = b_ih[j],     cz = b_ih[64+j],  cn = b_ih[128+j];

    for (int t = 0; t < T_STEPS; t++) {
        __syncthreads();
        for (int idx = tid; idx < 64*GNODES; idx += 256) {
            int m = idx >> 6, k = idx & 63;
            int node = nb + m;
            zs[k][m] = (node < NN) ? d_Z[(size_t)node*FTOT + t*EMB + k] : 0.f;
        }
        __syncthreads();

        float ir[8], iz[8], inx[8], hr[8], hz[8], hn[8];
        #pragma unroll
        for (int m = 0; m < 8; m++) { ir[m]=iz[m]=inx[m]=hr[m]=hz[m]=hn[m]=0.f; }

        #pragma unroll 4
        for (int k = 0; k < EMB; k++) {
            const float* wi = &d_WtIH[k*G3];
            const float* wh = &d_WtHH[k*G3];
            float wir = wi[j], wiz = wi[64+j], win = wi[128+j];
            float whr = wh[j], whz = wh[64+j], whn = wh[128+j];
            float4 za = *(const float4*)&zs[k][nlo];
            float4 zb = *(const float4*)&zs[k][nlo+4];
            float4 ha = *(const float4*)&hs[k][nlo];
            float4 hb = *(const float4*)&hs[k][nlo+4];
            float zv[8] = {za.x,za.y,za.z,za.w,zb.x,zb.y,zb.z,zb.w};
            float hv[8] = {ha.x,ha.y,ha.z,ha.w,hb.x,hb.y,hb.z,hb.w};
            #pragma unroll
            for (int m = 0; m < 8; m++) {
                ir[m]  += zv[m]*wir;  iz[m] += zv[m]*wiz;  inx[m] += zv[m]*win;
                hr[m]  += hv[m]*whr;  hz[m] += hv[m]*whz;  hn[m]  += hv[m]*whn;
            }
        }
        __syncthreads();
        #pragma unroll
        for (int m = 0; m < 8; m++) {
            float r  = 1.f/(1.f + __expf(-(ir[m] + cr + hr[m] + br)));
            float zg = 1.f/(1.f + __expf(-(iz[m] + cz + hz[m] + bz)));
            float ng = tanhf(inx[m] + cn + r*(hn[m] + bn));
            float ho = hs[j][nlo + m];
            hs[j][nlo + m] = (1.f - zg)*ng + zg*ho;
        }
    }
    __syncthreads();
    for (int idx = tid; idx < 64*GNODES; idx += 256) {
        int m = idx >> 6, k = idx & 63;
        int node = nb + m;
        if (node < NN) {
            float v = hs[k][m];
            d_h[(size_t)node*EMB + k] = v;
            out[(size_t)NN*NN + (size_t)node*EMB + k] = v;
        }
    }
}

// ---------------- split z into bf16 hi/lo ----------------
__global__ void k_split() {
    int idx = blockIdx.x*blockDim.x + threadIdx.x;
    if (idx >= NNP*EMB) return;
    int n = idx >> 6;
    float z = (n < NN) ? d_h[idx] : 0.f;
    __nv_bfloat16 a = __float2bfloat16(z);
    d_Za[idx] = a;
    d_Zb[idx] = __float2bfloat16(z - __bfloat162float(a));
}

// ---------------- mma.sync decoder: softplus(z z^T + b), symmetric ----------------
// Dynamic smem: 4 tiles of 128 x 64 bf16 (row stride 72 bf16 = 144B) = 73728 B.
// Epilogue stage (128 x 64 f32, stride 65) reuses the same memory (33280 B).
#define TS_B    144                     // tile row stride bytes
#define TILE_B  (128*TS_B)              // 18432
#define DEC_SMEM (4*TILE_B)             // 73728
__global__ void __launch_bounds__(256)
k_dectc(float* __restrict__ out, const float* __restrict__ db) {
    int bi = blockIdx.y, bj = blockIdx.x;
    if (bi > bj) return;
    extern __shared__ __align__(16) char smem[];
    uint32_t sb = s2u(smem);
    uint32_t* sm32 = (uint32_t*)smem;
    float* stage = (float*)smem;

    int tid = threadIdx.x;
    int wid = tid >> 5, lane = tid & 31;
    int wm = wid >> 2, wn = wid & 3;       // warp grid 2(M) x 4(N); warp tile 64x32

    int i0 = bi*128, j0 = bj*128;
    const uint32_t* za32 = (const uint32_t*)d_Za;
    const uint32_t* zb32 = (const uint32_t*)d_Zb;

    // load tiles: Aa(0) Ab(1) Ba(2) Bb(3); rows K-contiguous, u32 cols 0..31
    for (int idx = tid; idx < 4096; idx += 256) {
        int r = idx >> 5, c = idx & 31;
        int base = r*36 + c;               // u32 units, stride 36 = 72 bf16
        sm32[base]                 = za32[(size_t)(i0+r)*32 + c];
        sm32[base + TILE_B/4]      = zb32[(size_t)(i0+r)*32 + c];
        sm32[base + 2*(TILE_B/4)]  = za32[(size_t)(j0+r)*32 + c];
        sm32[base + 3*(TILE_B/4)]  = zb32[(size_t)(j0+r)*32 + c];
    }
    __syncthreads();

    float acc[4][4][4];
    #pragma unroll
    for (int mf = 0; mf < 4; mf++)
        #pragma unroll
        for (int nf = 0; nf < 4; nf++)
            #pragma unroll
            for (int q = 0; q < 4; q++) acc[mf][nf][q] = 0.f;

    // per-lane ldmatrix base offsets
    // A frag (m16k16): lanes 0-15 -> rows +0..15, lanes 16-31 -> same rows, k+8
    uint32_t aRow = wm*64 + (lane & 15);
    uint32_t aKb  = (lane >> 4) * 16;                       // bytes
    // B frag-pair (n16k16): lanes 0-7:n0-7 k0 | 8-15:n0-7 k8 | 16-23:n8-15 k0 | 24-31:n8-15 k8
    uint32_t bRow = wn*32 + (lane & 7) + ((lane >> 4) << 3);
    uint32_t bKb  = ((lane >> 3) & 1) * 16;

    uint32_t adAa = sb + aRow*TS_B + aKb;
    uint32_t adAb = adAa + TILE_B;
    uint32_t adBa = sb + 2*TILE_B + bRow*TS_B + bKb;
    uint32_t adBb = adBa + TILE_B;

    #pragma unroll
    for (int ks = 0; ks < 4; ks++) {
        uint32_t kof = ks*32;
        uint32_t Aa[4][4], Ab[4][4], Ba[4][2], Bb[4][2];
        #pragma unroll
        for (int mf = 0; mf < 4; mf++) {
            LDM4(Aa[mf][0], Aa[mf][1], Aa[mf][2], Aa[mf][3], adAa + mf*16*TS_B + kof);
            LDM4(Ab[mf][0], Ab[mf][1], Ab[mf][2], Ab[mf][3], adAb + mf*16*TS_B + kof);
        }
        #pragma unroll
        for (int np = 0; np < 2; np++) {
            LDM4(Ba[np*2][0], Ba[np*2][1], Ba[np*2+1][0], Ba[np*2+1][1], adBa + np*16*TS_B + kof);
            LDM4(Bb[np*2][0], Bb[np*2][1], Bb[np*2+1][0], Bb[np*2+1][1], adBb + np*16*TS_B + kof);
        }
        #pragma unroll
        for (int mf = 0; mf < 4; mf++)
            #pragma unroll
            for (int nf = 0; nf < 4; nf++) {
                MMA16816(acc[mf][nf], Aa[mf], Ba[nf]);
                MMA16816(acc[mf][nf], Aa[mf], Bb[nf]);
                MMA16816(acc[mf][nf], Ab[mf], Ba[nf]);
            }
    }
    __syncthreads();   // tiles dead; stage reuses smem

    float bias = db[0];
    bool diag = (bi == bj);
    int l4 = lane >> 2, l2 = (lane & 3) * 2;

    #pragma unroll
    for (int h = 0; h < 2; h++) {
        if ((wn >> 1) == h) {
            int cb = (wn & 1)*32;
            #pragma unroll
            for (int mf = 0; mf < 4; mf++) {
                int rB = wm*64 + mf*16 + l4;
                #pragma unroll
                for (int nf = 0; nf < 4; nf++) {
                    int cB = cb + nf*8 + l2;
                    #pragma unroll
                    for (int q = 0; q < 4; q++) {
                        float x = acc[mf][nf][q] + bias;
                        x = fmaxf(x, 0.f) + __logf(1.f + __expf(-fabsf(x)));
                        int rr = rB + ((q >> 1) << 3);
                        int cc = cB + (q & 1);
                        stage[rr*65 + cc] = x;
                    }
                }
            }
        }
        __syncthreads();
        // direct store: rows i0.., cols j0+h*64.. (coalesced 64-wide)
        for (int idx = tid; idx < 8192; idx += 256) {
            int c = idx & 63, r = idx >> 6;
            int gi = i0 + r, gj = j0 + h*64 + c;
            if (gi < NN && gj < NN) out[(size_t)gi*NN + gj] = stage[r*65 + c];
        }
        // mirror store: transposed (coalesced over r; stride-65 column reads conflict-free)
        if (!diag) {
            for (int idx = tid; idx < 8192; idx += 256) {
                int r = idx & 127, c = idx >> 7;
                int gi = i0 + r, gj = j0 + h*64 + c;
                if (gi < NN && gj < NN) out[(size_t)gj*NN + gi] = stage[r*65 + c];
            }
        }
        __syncthreads();
    }
}

// ---------------- launch ----------------
extern "C" void kernel_launch(void* const* d_in, const int* in_sizes, int n_in,
                              void* d_out, int out_size) {
    const float* x_seq = (const float*)d_in[0];
    const int*   ei    = (const int*)d_in[1];
    const float* ew    = (const float*)d_in[2];
    const float* W1    = (const float*)d_in[3];
    const float* b1    = (const float*)d_in[4];
    const float* W2    = (const float*)d_in[5];
    const float* b2    = (const float*)d_in[6];
    const float* W_ih  = (const float*)d_in[7];
    const float* W_hh  = (const float*)d_in[8];
    const float* b_ih  = (const float*)d_in[9];
    const float* b_hh  = (const float*)d_in[10];
    const float* dbias = (const float*)d_in[11];
    float* out = (float*)d_out;

    float *pAX, *pH1, *pH2;
    cudaGetSymbolAddress((void**)&pAX, d_AX);
    cudaGetSymbolAddress((void**)&pH1, d_H1);
    cudaGetSymbolAddress((void**)&pH2, d_H2);

    cudaFuncSetAttribute(k_dectc, cudaFuncAttributeMaxDynamicSharedMemorySize, DEC_SMEM);

    // preprocessing
    k_init<<<(NN + 255)/256, 256>>>();
    k_deg_hist<<<(NE + 255)/256, 256>>>(ei, ew);
    k_rsqrt<<<(NN + 255)/256, 256>>>();
    k_scan<<<1, 1024>>>();
    k_scatter<<<(NE + 255)/256, 256>>>(ei, ew);
    k_transposeW<<<(G3*EMB + 255)/256, 256>>>(W_ih, W_hh);

    // encoder
    k_spmmX<<<dim3(NN, FTOT/256), 256>>>(x_seq);
    k_gemmT<IN_DIM, 1><<<dim3(NROWSP/128, 2), 256>>>(pAX, W1, b1, pH1, HID);
    k_gemmT<HID,    0><<<dim3(NROWSP/128, 1), 256>>>(pH1, W2, nullptr, pH2, EMB);
    k_spmmZ<<<dim3(NN, FTOT/256), 256>>>(b2);

    // fused GRU (also writes z tail of output)
    k_gruF<<<(NN + GNODES - 1)/GNODES, 256>>>(b_ih, b_hh, out);

    // decoder: bf16-split mma.sync GEMM, symmetric
    k_split<<<(NNP*EMB + 255)/256, 256>>>();
    const int NT = NNP/128;   // 79
    k_dectc<<<dim3(NT, NT), 256, DEC_SMEM>>>(out, dbias);
}

// round 11
// speedup vs baseline: 1.6891x; 1.0059x over previous
#include <cuda_runtime.h>
#include <cuda_bf16.h>
#include <math.h>
#include <stdint.h>

#define T_STEPS 12
#define NN      10000
#define NE      320000
#define IN_DIM  64
#define HID     128
#define EMB     64
#define G3      192             // 3*EMB
#define FTOT    (T_STEPS*EMB)   // 768
#define NROWS   (NN*T_STEPS)    // 120000
#define NROWSP  120064
#define GNODES  32
#define NNP     10112           // 79*128

typedef unsigned long long u64t;

// ---------------- scratch ----------------
__device__ float d_dinv[NN];
__device__ int   d_cnt[NN];
__device__ int   d_off[NN+1];
__device__ int   d_fill[NN];
__device__ int   d_src[NE];
__device__ float d_w[NE];
__device__ float d_AX[(size_t)NROWSP*IN_DIM];
__device__ float d_H1[(size_t)NROWSP*HID];
__device__ float d_H2[(size_t)NROWSP*EMB];
__device__ float d_Z [(size_t)NROWSP*EMB];
__device__ float d_WtIH[EMB*G3];
__device__ float d_WtHH[EMB*G3];
__device__ __nv_bfloat16 d_Za[(size_t)NNP*EMB];   // hi part of z (padding stays 0)
__device__ __nv_bfloat16 d_Zb[(size_t)NNP*EMB];   // lo part of z

// ---------------- asm helpers ----------------
static __device__ __forceinline__ uint32_t s2u(const void* p) {
    uint32_t a;
    asm("{ .reg .u64 t; cvta.to.shared.u64 t, %1; cvt.u32.u64 %0, t; }" : "=r"(a) : "l"(p));
    return a;
}
#define LDM4(r0,r1,r2,r3,addr) \
    asm volatile("ldmatrix.sync.aligned.m8n8.x4.shared.b16 {%0,%1,%2,%3}, [%4];" \
        : "=r"(r0), "=r"(r1), "=r"(r2), "=r"(r3) : "r"(addr))
#define MMA16816(c, a, b) \
    asm volatile("mma.sync.aligned.m16n8k16.row.col.f32.bf16.bf16.f32 " \
        "{%0,%1,%2,%3}, {%4,%5,%6,%7}, {%8,%9}, {%0,%1,%2,%3};" \
        : "+f"((c)[0]), "+f"((c)[1]), "+f"((c)[2]), "+f"((c)[3]) \
        : "r"((a)[0]), "r"((a)[1]), "r"((a)[2]), "r"((a)[3]), "r"((b)[0]), "r"((b)[1]))
// packed fp32x2
#define FMA2(c, a, b) asm("fma.rn.f32x2 %0, %1, %2, %0;" : "+l"(c) : "l"(a), "l"(b))
#define PACK2(d, lo, hi) asm("mov.b64 %0, {%1, %2};" : "=l"(d) : "f"(lo), "f"(hi))
#define UNPACK2(lo, hi, s) asm("mov.b64 {%0, %1}, %2;" : "=f"(lo), "=f"(hi) : "l"(s))

// ---------------- preprocessing ----------------
__global__ void k_init() {
    int i = blockIdx.x*blockDim.x + threadIdx.x;
    if (i < NN) { d_dinv[i] = 1.0f; d_cnt[i] = 0; }
}

__global__ void k_deg_hist(const int* __restrict__ ei, const float* __restrict__ ew) {
    int e = blockIdx.x*blockDim.x + threadIdx.x;
    if (e >= NE) return;
    int c = ei[NE + e];
    atomicAdd(&d_dinv[c], ew[e]);
    atomicAdd(&d_cnt[c], 1);
}

// scan + rsqrt + weight transpose fused (single block, 1024 threads)
__global__ void k_scan(const float* __restrict__ W_ih, const float* __restrict__ W_hh) {
    __shared__ int warpsum[32];
    int tid = threadIdx.x;
    int vals[10];
    int s = 0;
    #pragma unroll
    for (int i = 0; i < 10; i++) {
        int idx = tid*10 + i;
        int v = (idx < NN) ? d_cnt[idx] : 0;
        vals[i] = s;
        s += v;
    }
    int lane = tid & 31, wid = tid >> 5;
    int tot = s;
    #pragma unroll
    for (int o = 1; o < 32; o <<= 1) {
        int n = __shfl_up_sync(0xffffffffu, tot, o);
        if (lane >= o) tot += n;
    }
    if (lane == 31) warpsum[wid] = tot;
    __syncthreads();
    if (wid == 0) {
        int w = warpsum[lane];
        #pragma unroll
        for (int o = 1; o < 32; o <<= 1) {
            int n = __shfl_up_sync(0xffffffffu, w, o);
            if (lane >= o) w += n;
        }
        warpsum[lane] = w;
    }
    __syncthreads();
    int base = tot - s + (wid ? warpsum[wid-1] : 0);
    #pragma unroll
    for (int i = 0; i < 10; i++) {
        int idx = tid*10 + i;
        if (idx < NN) {
            int o = base + vals[i];
            d_off[idx] = o; d_fill[idx] = o;
            d_dinv[idx] = rsqrtf(d_dinv[idx]);
        }
    }
    if (tid == 1023) d_off[NN] = base + s;
    // transpose GRU weights (independent work)
    for (int i = tid; i < G3*EMB; i += 1024) {
        int j = i >> 6, k = i & 63;
        d_WtIH[k*G3 + j] = W_ih[i];
        d_WtHH[k*G3 + j] = W_hh[i];
    }
}

__global__ void k_scatter(const int* __restrict__ ei, const float* __restrict__ ew) {
    int e = blockIdx.x*blockDim.x + threadIdx.x;
    if (e >= NE) return;
    int r = ei[e];
    int c = ei[NE + e];
    float nm = d_dinv[r] * ew[e] * d_dinv[c];
    int pos = atomicAdd(&d_fill[c], 1);
    d_src[pos] = r;
    d_w[pos]   = nm;
}

// ---------------- batched SpMM: AX = Â X ----------------
__global__ void k_spmmX(const float* __restrict__ X) {
    int d = blockIdx.x;
    int j = blockIdx.y*256 + threadIdx.x;
    int t = j >> 6, k = j & 63;
    const float* Xt = X + (size_t)t*NN*IN_DIM + k;
    float di = d_dinv[d];
    float acc = di*di * Xt[(size_t)d*IN_DIM];
    int beg = d_off[d], end = d_off[d+1];
    int p = beg;
    for (; p + 4 <= end; p += 4) {
        int   s0 = d_src[p],   s1 = d_src[p+1], s2 = d_src[p+2], s3 = d_src[p+3];
        float w0 = d_w[p],     w1 = d_w[p+1],   w2 = d_w[p+2],   w3 = d_w[p+3];
        float x0 = Xt[(size_t)s0*IN_DIM];
        float x1 = Xt[(size_t)s1*IN_DIM];
        float x2 = Xt[(size_t)s2*IN_DIM];
        float x3 = Xt[(size_t)s3*IN_DIM];
        acc += w0*x0; acc += w1*x1; acc += w2*x2; acc += w3*x3;
    }
    for (; p < end; p++) acc += d_w[p] * Xt[(size_t)d_src[p]*IN_DIM];
    d_AX[(size_t)(d*T_STEPS + t)*IN_DIM + k] = acc;
}

// ---------------- tiled GEMM (f32x2): C = act(A@B + bias) ----------------
template<int K, int ACT>
__global__ void __launch_bounds__(256)
k_gemmT(const float* __restrict__ A, const float* __restrict__ B,
        const float* __restrict__ bias, float* __restrict__ C, int N) {
    __shared__ float As[32][132];
    __shared__ float Bs[32][64];
    int tid = threadIdx.x;
    int tr = tid >> 4, tc = tid & 15;
    int row0 = blockIdx.x * 128;
    int col0 = blockIdx.y * 64;
    u64t acc2[4][4];                   // row-pairs (u) x cols (v)
    #pragma unroll
    for (int u = 0; u < 4; u++)
        #pragma unroll
        for (int v = 0; v < 4; v++) acc2[u][v] = 0ull;

    #pragma unroll
    for (int k0 = 0; k0 < K; k0 += 32) {
        #pragma unroll
        for (int p = 0; p < 4; p++) {
            int idx = p*256 + tid;
            int r = idx >> 3, k4 = (idx & 7)*4;
            float4 av = *(const float4*)&A[(size_t)(row0 + r)*K + k0 + k4];
            As[k4+0][r] = av.x; As[k4+1][r] = av.y;
            As[k4+2][r] = av.z; As[k4+3][r] = av.w;
        }
        #pragma unroll
        for (int p = 0; p < 2; p++) {
            int idx = p*256 + tid;
            int kk = idx >> 4, c4 = (idx & 15)*4;
            float4 bv = *(const float4*)&B[(size_t)(k0 + kk)*N + col0 + c4];
            *(float4*)&Bs[kk][c4] = bv;
        }
        __syncthreads();
        #pragma unroll
        for (int k = 0; k < 32; k++) {
            ulonglong2 ap0 = *(const ulonglong2*)&As[k][tr*8];
            ulonglong2 ap1 = *(const ulonglong2*)&As[k][tr*8 + 4];
            u64t aq[4] = {ap0.x, ap0.y, ap1.x, ap1.y};
            float4 b0 = *(const float4*)&Bs[k][tc*4];
            u64t bq[4];
            PACK2(bq[0], b0.x, b0.x); PACK2(bq[1], b0.y, b0.y);
            PACK2(bq[2], b0.z, b0.z); PACK2(bq[3], b0.w, b0.w);
            #pragma unroll
            for (int u = 0; u < 4; u++)
                #pragma unroll
                for (int v = 0; v < 4; v++) FMA2(acc2[u][v], aq[u], bq[v]);
        }
        __syncthreads();
    }

    float bb[4] = {0.f,0.f,0.f,0.f};
    if (bias) {
        #pragma unroll
        for (int v = 0; v < 4; v++) bb[v] = bias[col0 + tc*4 + v];
    }
    #pragma unroll
    for (int u = 0; u < 4; u++) {
        float lo[4], hi[4];
        #pragma unroll
        for (int v = 0; v < 4; v++) UNPACK2(lo[v], hi[v], acc2[u][v]);
        int r = row0 + tr*8 + u*2;
        float x0, x1, x2, x3;
        x0 = lo[0]+bb[0]; x1 = lo[1]+bb[1]; x2 = lo[2]+bb[2]; x3 = lo[3]+bb[3];
        if (ACT) { x0 = fmaxf(x0,0.f); x1 = fmaxf(x1,0.f); x2 = fmaxf(x2,0.f); x3 = fmaxf(x3,0.f); }
        *(float4*)&C[(size_t)r*N + col0 + tc*4] = make_float4(x0,x1,x2,x3);
        x0 = hi[0]+bb[0]; x1 = hi[1]+bb[1]; x2 = hi[2]+bb[2]; x3 = hi[3]+bb[3];
        if (ACT) { x0 = fmaxf(x0,0.f); x1 = fmaxf(x1,0.f); x2 = fmaxf(x2,0.f); x3 = fmaxf(x3,0.f); }
        *(float4*)&C[(size_t)(r+1)*N + col0 + tc*4] = make_float4(x0,x1,x2,x3);
    }
}

// ---------------- batched SpMM: Z = Â H2 + b2 ----------------
__global__ void k_spmmZ(const float* __restrict__ b2) {
    int d = blockIdx.x;
    int j = blockIdx.y*256 + threadIdx.x;
    int t = j >> 6, k = j & 63;
    const float* H = d_H2 + (size_t)t*EMB + k;
    float di = d_dinv[d];
    float acc = di*di * H[(size_t)d*FTOT];
    int beg = d_off[d], end = d_off[d+1];
    int p = beg;
    for (; p + 4 <= end; p += 4) {
        int   s0 = d_src[p],   s1 = d_src[p+1], s2 = d_src[p+2], s3 = d_src[p+3];
        float w0 = d_w[p],     w1 = d_w[p+1],   w2 = d_w[p+2],   w3 = d_w[p+3];
        float x0 = H[(size_t)s0*FTOT];
        float x1 = H[(size_t)s1*FTOT];
        float x2 = H[(size_t)s2*FTOT];
        float x3 = H[(size_t)s3*FTOT];
        acc += w0*x0; acc += w1*x1; acc += w2*x2; acc += w3*x3;
    }
    for (; p < end; p++) acc += d_w[p] * H[(size_t)d_src[p]*FTOT];
    d_Z[(size_t)d*FTOT + t*EMB + k] = acc + b2[k];
}

// ---------------- fused GRU (f32x2 inner loops) + bf16 split epilogue ----------------
__global__ void __launch_bounds__(256)
k_gruF(const float* __restrict__ b_ih, const float* __restrict__ b_hh,
       float* __restrict__ out) {
    __shared__ float hs[64][GNODES+4];
    __shared__ float zs[64][GNODES+4];
    int tid = threadIdx.x;
    int j = tid & 63;
    int g = tid >> 6;
    int nlo = g * 8;
    int nb = blockIdx.x * GNODES;

    for (int idx = tid; idx < 64*GNODES; idx += 256) {
        int m = idx >> 6, k = idx & 63;
        hs[k][m] = 0.f;
    }

    float br = b_hh[j],     bz = b_hh[64+j],  bn = b_hh[128+j];
    float cr = b_ih[j],     cz = b_ih[64+j],  cn = b_ih[128+j];

    for (int t = 0; t < T_STEPS; t++) {
        __syncthreads();
        for (int idx = tid; idx < 64*GNODES; idx += 256) {
            int m = idx >> 6, k = idx & 63;
            int node = nb + m;
            zs[k][m] = (node < NN) ? d_Z[(size_t)node*FTOT + t*EMB + k] : 0.f;
        }
        __syncthreads();

        u64t ir2[4], iz2[4], in2[4], hr2[4], hz2[4], hn2[4];
        #pragma unroll
        for (int m = 0; m < 4; m++) { ir2[m]=iz2[m]=in2[m]=hr2[m]=hz2[m]=hn2[m]=0ull; }

        #pragma unroll 4
        for (int k = 0; k < EMB; k++) {
            const float* wi = &d_WtIH[k*G3];
            const float* wh = &d_WtHH[k*G3];
            float wir = wi[j], wiz = wi[64+j], win = wi[128+j];
            float whr = wh[j], whz = wh[64+j], whn = wh[128+j];
            u64t wir2, wiz2, win2, whr2, whz2, whn2;
            PACK2(wir2, wir, wir); PACK2(wiz2, wiz, wiz); PACK2(win2, win, win);
            PACK2(whr2, whr, whr); PACK2(whz2, whz, whz); PACK2(whn2, whn, whn);
            ulonglong2 zp0 = *(const ulonglong2*)&zs[k][nlo];
            ulonglong2 zp1 = *(const ulonglong2*)&zs[k][nlo+4];
            ulonglong2 hp0 = *(const ulonglong2*)&hs[k][nlo];
            ulonglong2 hp1 = *(const ulonglong2*)&hs[k][nlo+4];
            u64t zq[4] = {zp0.x, zp0.y, zp1.x, zp1.y};
            u64t hq[4] = {hp0.x, hp0.y, hp1.x, hp1.y};
            #pragma unroll
            for (int m = 0; m < 4; m++) {
                FMA2(ir2[m], zq[m], wir2);
                FMA2(iz2[m], zq[m], wiz2);
                FMA2(in2[m], zq[m], win2);
                FMA2(hr2[m], hq[m], whr2);
                FMA2(hz2[m], hq[m], whz2);
                FMA2(hn2[m], hq[m], whn2);
            }
        }
        float ir[8], iz[8], inx[8], hr[8], hz[8], hn[8];
        #pragma unroll
        for (int m = 0; m < 4; m++) {
            UNPACK2(ir[2*m],  ir[2*m+1],  ir2[m]);
            UNPACK2(iz[2*m],  iz[2*m+1],  iz2[m]);
            UNPACK2(inx[2*m], inx[2*m+1], in2[m]);
            UNPACK2(hr[2*m],  hr[2*m+1],  hr2[m]);
            UNPACK2(hz[2*m],  hz[2*m+1],  hz2[m]);
            UNPACK2(hn[2*m],  hn[2*m+1],  hn2[m]);
        }
        __syncthreads();
        #pragma unroll
        for (int m = 0; m < 8; m++) {
            float r  = 1.f/(1.f + __expf(-(ir[m] + cr + hr[m] + br)));
            float zg = 1.f/(1.f + __expf(-(iz[m] + cz + hz[m] + bz)));
            float ng = tanhf(inx[m] + cn + r*(hn[m] + bn));
            float ho = hs[j][nlo + m];
            hs[j][nlo + m] = (1.f - zg)*ng + zg*ho;
        }
    }
    __syncthreads();
    // epilogue: write output tail + bf16 hi/lo split for the decoder
    for (int idx = tid; idx < 64*GNODES; idx += 256) {
        int m = idx >> 6, k = idx & 63;
        int node = nb + m;
        if (node < NN) {
            float v = hs[k][m];
            out[(size_t)NN*NN + (size_t)node*EMB + k] = v;
            __nv_bfloat16 a = __float2bfloat16(v);
            d_Za[(size_t)node*EMB + k] = a;
            d_Zb[(size_t)node*EMB + k] = __float2bfloat16(v - __bfloat162float(a));
        }
    }
}

// ---------------- mma.sync decoder: softplus(z z^T + b), symmetric ----------------
#define TS_B    144
#define TILE_B  (128*TS_B)
#define DEC_SMEM (4*TILE_B)
__global__ void __launch_bounds__(256)
k_dectc(float* __restrict__ out, const float* __restrict__ db) {
    int bi = blockIdx.y, bj = blockIdx.x;
    if (bi > bj) return;
    extern __shared__ __align__(16) char smem[];
    uint32_t sb = s2u(smem);
    uint32_t* sm32 = (uint32_t*)smem;
    float* stage = (float*)smem;

    int tid = threadIdx.x;
    int wid = tid >> 5, lane = tid & 31;
    int wm = wid >> 2, wn = wid & 3;

    int i0 = bi*128, j0 = bj*128;
    const uint32_t* za32 = (const uint32_t*)d_Za;
    const uint32_t* zb32 = (const uint32_t*)d_Zb;

    for (int idx = tid; idx < 4096; idx += 256) {
        int r = idx >> 5, c = idx & 31;
        int base = r*36 + c;
        sm32[base]                 = za32[(size_t)(i0+r)*32 + c];
        sm32[base + TILE_B/4]      = zb32[(size_t)(i0+r)*32 + c];
        sm32[base + 2*(TILE_B/4)]  = za32[(size_t)(j0+r)*32 + c];
        sm32[base + 3*(TILE_B/4)]  = zb32[(size_t)(j0+r)*32 + c];
    }
    __syncthreads();

    float acc[4][4][4];
    #pragma unroll
    for (int mf = 0; mf < 4; mf++)
        #pragma unroll
        for (int nf = 0; nf < 4; nf++)
            #pragma unroll
            for (int q = 0; q < 4; q++) acc[mf][nf][q] = 0.f;

    uint32_t aRow = wm*64 + (lane & 15);
    uint32_t aKb  = (lane >> 4) * 16;
    uint32_t bRow = wn*32 + (lane & 7) + ((lane >> 4) << 3);
    uint32_t bKb  = ((lane >> 3) & 1) * 16;

    uint32_t adAa = sb + aRow*TS_B + aKb;
    uint32_t adAb = adAa + TILE_B;
    uint32_t adBa = sb + 2*TILE_B + bRow*TS_B + bKb;
    uint32_t adBb = adBa + TILE_B;

    #pragma unroll
    for (int ks = 0; ks < 4; ks++) {
        uint32_t kof = ks*32;
        uint32_t Aa[4][4], Ab[4][4], Ba[4][2], Bb[4][2];
        #pragma unroll
        for (int mf = 0; mf < 4; mf++) {
            LDM4(Aa[mf][0], Aa[mf][1], Aa[mf][2], Aa[mf][3], adAa + mf*16*TS_B + kof);
            LDM4(Ab[mf][0], Ab[mf][1], Ab[mf][2], Ab[mf][3], adAb + mf*16*TS_B + kof);
        }
        #pragma unroll
        for (int np = 0; np < 2; np++) {
            LDM4(Ba[np*2][0], Ba[np*2][1], Ba[np*2+1][0], Ba[np*2+1][1], adBa + np*16*TS_B + kof);
            LDM4(Bb[np*2][0], Bb[np*2][1], Bb[np*2+1][0], Bb[np*2+1][1], adBb + np*16*TS_B + kof);
        }
        #pragma unroll
        for (int mf = 0; mf < 4; mf++)
            #pragma unroll
            for (int nf = 0; nf < 4; nf++) {
                MMA16816(acc[mf][nf], Aa[mf], Ba[nf]);
                MMA16816(acc[mf][nf], Aa[mf], Bb[nf]);
                MMA16816(acc[mf][nf], Ab[mf], Ba[nf]);
            }
    }
    __syncthreads();

    float bias = db[0];
    bool diag = (bi == bj);
    int l4 = lane >> 2, l2 = (lane & 3) * 2;

    #pragma unroll
    for (int h = 0; h < 2; h++) {
        if ((wn >> 1) == h) {
            int cb = (wn & 1)*32;
            #pragma unroll
            for (int mf = 0; mf < 4; mf++) {
                int rB = wm*64 + mf*16 + l4;
                #pragma unroll
                for (int nf = 0; nf < 4; nf++) {
                    int cB = cb + nf*8 + l2;
                    #pragma unroll
                    for (int q = 0; q < 4; q++) {
                        float x = acc[mf][nf][q] + bias;
                        x = fmaxf(x, 0.f) + __logf(1.f + __expf(-fabsf(x)));
                        int rr = rB + ((q >> 1) << 3);
                        int cc = cB + (q & 1);
                        stage[rr*65 + cc] = x;
                    }
                }
            }
        }
        __syncthreads();
        for (int idx = tid; idx < 8192; idx += 256) {
            int c = idx & 63, r = idx >> 6;
            int gi = i0 + r, gj = j0 + h*64 + c;
            if (gi < NN && gj < NN) out[(size_t)gi*NN + gj] = stage[r*65 + c];
        }
        if (!diag) {
            for (int idx = tid; idx < 8192; idx += 256) {
                int r = idx & 127, c = idx >> 7;
                int gi = i0 + r, gj = j0 + h*64 + c;
                if (gi < NN && gj < NN) out[(size_t)gj*NN + gi] = stage[r*65 + c];
            }
        }
        __syncthreads();
    }
}

// ---------------- launch ----------------
extern "C" void kernel_launch(void* const* d_in, const int* in_sizes, int n_in,
                              void* d_out, int out_size) {
    const float* x_seq = (const float*)d_in[0];
    const int*   ei    = (const int*)d_in[1];
    const float* ew    = (const float*)d_in[2];
    const float* W1    = (const float*)d_in[3];
    const float* b1    = (const float*)d_in[4];
    const float* W2    = (const float*)d_in[5];
    const float* b2    = (const float*)d_in[6];
    const float* W_ih  = (const float*)d_in[7];
    const float* W_hh  = (const float*)d_in[8];
    const float* b_ih  = (const float*)d_in[9];
    const float* b_hh  = (const float*)d_in[10];
    const float* dbias = (const float*)d_in[11];
    float* out = (float*)d_out;

    float *pAX, *pH1, *pH2;
    cudaGetSymbolAddress((void**)&pAX, d_AX);
    cudaGetSymbolAddress((void**)&pH1, d_H1);
    cudaGetSymbolAddress((void**)&pH2, d_H2);

    cudaFuncSetAttribute(k_dectc, cudaFuncAttributeMaxDynamicSharedMemorySize, DEC_SMEM);

    // preprocessing (scan also does rsqrt + weight transpose)
    k_init<<<(NN + 255)/256, 256>>>();
    k_deg_hist<<<(NE + 255)/256, 256>>>(ei, ew);
    k_scan<<<1, 1024>>>(W_ih, W_hh);
    k_scatter<<<(NE + 255)/256, 256>>>(ei, ew);

    // encoder
    k_spmmX<<<dim3(NN, FTOT/256), 256>>>(x_seq);
    k_gemmT<IN_DIM, 1><<<dim3(NROWSP/128, 2), 256>>>(pAX, W1, b1, pH1, HID);
    k_gemmT<HID,    0><<<dim3(NROWSP/128, 1), 256>>>(pH1, W2, nullptr, pH2, EMB);
    k_spmmZ<<<dim3(NN, FTOT/256), 256>>>(b2);

    // fused GRU (writes output tail + bf16 split directly)
    k_gruF<<<(NN + GNODES - 1)/GNODES, 256>>>(b_ih, b_hh, out);

    // decoder: bf16-split mma.sync GEMM, symmetric
    const int NT = NNP/128;   // 79
    k_dectc<<<dim3(NT, NT), 256, DEC_SMEM>>>(out, dbias);
}